// round 14
// baseline (speedup 1.0000x reference)
#include <cuda_runtime.h>
#include <cuda_fp16.h>
#include <math.h>
#include <stdint.h>

#define BB 512
#define SS 30
#define CC 16
#define HH 768
#define NW 3840
#define NSLOT 15360
#define NCLS 8192
#define NROW 23552
#define EPSV 1e-5f

// GEMM tiling (fp16 single-term HMMA) — round-13 validated skeleton
#define BM 128
#define BN 128
#define BK 32
#define NTHREADS 256
#define TILE_BYTES (128*32*2)           // 8192 per matrix tile
#define OFF_A 0
#define OFF_B TILE_BYTES
#define STAGE  (2*TILE_BYTES)           // 16384
#define NSTAGE 3
#define SMEM_TOTAL (NSTAGE*STAGE)       // 49152 -> 2 CTAs/SM

// ---------------- scratch (__device__ globals; no allocations) ----------------
__device__ __align__(128) float  g_X[2][(size_t)NROW*HH];
__device__ __align__(128) __half g_Xh[2][(size_t)NROW*HH];
__device__ __align__(128) float  g_U[(size_t)NROW*HH];
__device__ __align__(128) __half g_Uh[(size_t)NROW*HH];
__device__ __align__(128) float  g_Y[(size_t)NROW*NW];
__device__ __align__(128) __half g_Wth[(size_t)NW*HH];      // [NW][HH]  B^T proj
__device__ __align__(128) __half g_Gth[(size_t)HH*2*HH];    // [HH][2*HH] B^T gate
__device__ float g_bcat[NW];

// ---------------- PTX helpers ----------------
__device__ __forceinline__ uint32_t s2u(const void* p) {
    uint32_t a;
    asm("{ .reg .u64 t; cvta.to.shared.u64 t, %1; cvt.u32.u64 %0, t; }" : "=r"(a) : "l"(p));
    return a;
}
__device__ __forceinline__ void cpa16(uint32_t s, const void* g) {
    asm volatile("cp.async.cg.shared.global [%0], [%1], 16;" :: "r"(s), "l"(g));
}
__device__ __forceinline__ void ldsm_x4(uint32_t addr, uint32_t* r) {
    asm volatile("ldmatrix.sync.aligned.m8n8.x4.shared.b16 {%0,%1,%2,%3}, [%4];"
        : "=r"(r[0]), "=r"(r[1]), "=r"(r[2]), "=r"(r[3]) : "r"(addr));
}
__device__ __forceinline__ void mma_f16(float* d, const uint32_t* a, const uint32_t* b) {
    asm volatile("mma.sync.aligned.m16n8k16.row.col.f32.f16.f16.f32 "
        "{%0,%1,%2,%3}, {%4,%5,%6,%7}, {%8,%9}, {%0,%1,%2,%3};"
        : "+f"(d[0]), "+f"(d[1]), "+f"(d[2]), "+f"(d[3])
        : "r"(a[0]), "r"(a[1]), "r"(a[2]), "r"(a[3]), "r"(b[0]), "r"(b[1]));
}

// half-row swizzle for 64B rows packed 2-per-128B line (validated):
__device__ __forceinline__ uint32_t swz64(int row, int c) {
    return (uint32_t)(((row >> 1) << 7) + (((((row & 1) << 2) + c) ^ ((row >> 1) & 7)) << 4));
}

// ---------------- init / pack ----------------
__global__ void k_init(const float* __restrict__ slots, const float* __restrict__ cls) {
    size_t i = (size_t)blockIdx.x * blockDim.x + threadIdx.x;
    if (i >= (size_t)NROW * HH) return;
    const size_t n0 = (size_t)NSLOT * HH;
    float v = (i < n0) ? slots[i] : cls[i - n0];
    g_X[0][i] = v;
    g_Xh[0][i] = __float2half_rn(v);
}
__global__ void k_packW(const float* __restrict__ Ws, const float* __restrict__ bs,
                        const float* __restrict__ Wr, const float* __restrict__ br) {
    size_t i = (size_t)blockIdx.x * blockDim.x + threadIdx.x;
    if (i < (size_t)NW * HH) {
        int j = (int)(i / HH);
        int h = (int)(i % HH);
        int p = j / HH;
        int n = j % HH;
        float w = (p == 0) ? Ws[(size_t)h * HH + n]
                           : Wr[((size_t)(p - 1) * HH + h) * HH + n];
        g_Wth[i] = __float2half_rn(w);
    }
    if (i < NW) {
        int p = (int)(i / HH), n = (int)(i % HH);
        g_bcat[i] = (p == 0) ? bs[n] : br[(size_t)(p - 1) * HH + n];
    }
}
__global__ void k_packG(const float* __restrict__ Wg) {
    size_t i = (size_t)blockIdx.x * blockDim.x + threadIdx.x;
    if (i >= (size_t)HH * 2 * HH) return;
    int j = (int)(i / (2 * HH));
    int k = (int)(i % (2 * HH));
    g_Gth[i] = __float2half_rn(Wg[(size_t)k * HH + j]);
}

// ---------------- stage loader: 128x32 fp16 tiles, half-row swizzled ----------------
__device__ __forceinline__ void load_tile(
    uint32_t stg, int tid,
    const __half* __restrict__ A, size_t a_row0, int a_ld, int ak,
    const __half* __restrict__ B, size_t b_row0, int b_ld, int bk) {
#pragma unroll
    for (int t = 0; t < 2; t++) {
        int id = tid + t * NTHREADS;
        int row = id >> 2, c = id & 3;
        uint32_t so = swz64(row, c);
        cpa16(stg + OFF_A + so, A + (a_row0 + row) * (size_t)a_ld + ak + (c << 3));
        cpa16(stg + OFF_B + so, B + (b_row0 + row) * (size_t)b_ld + bk + (c << 3));
    }
}

// ---------------- per-BK-tile compute: single-term fp16 ----------------
__device__ __forceinline__ void compute_tile(uint32_t stg, int wm, int wn, int lane,
                                             float acc[4][4][4]) {
#pragma unroll
    for (int kk = 0; kk < 2; kk++) {
        uint32_t bh[4][2];
        {
            int brow = wn * 32 + (lane >> 4) * 8 + (lane & 7);
            int bc = kk * 2 + ((lane >> 3) & 1);
            uint32_t base = swz64(brow, bc);
#pragma unroll
            for (int p = 0; p < 2; p++) {
                uint32_t r[4];
                ldsm_x4(stg + OFF_B + base + p * 1024, r);
                bh[2*p][0] = r[0]; bh[2*p][1] = r[1];
                bh[2*p+1][0] = r[2]; bh[2*p+1][1] = r[3];
            }
        }
        const int arow = wm * 64 + (lane & 15);
        const int ac = kk * 2 + (lane >> 4);
        uint32_t abase = swz64(arow, ac);
        uint32_t ah[4][4];
#pragma unroll
        for (int mt = 0; mt < 4; mt++)
            ldsm_x4(stg + OFF_A + abase + mt * 1024, ah[mt]);
#pragma unroll
        for (int mt = 0; mt < 4; mt++)
#pragma unroll
            for (int nt = 0; nt < 4; nt++)
                mma_f16(acc[mt][nt], ah[mt], bh[nt]);
    }
}

// ---------------- GEMM 1: Y = X @ Wcat + bcat ----------------
__global__ void __launch_bounds__(NTHREADS, 2) k_gemm_proj(int layer, int cls_mode) {
    extern __shared__ __align__(128) char smem[];
    uint32_t sb = s2u(smem);
    const int tid = threadIdx.x, lane = tid & 31, wid = tid >> 5;
    const int wm = wid >> 2, wn = wid & 3;
    int cb = blockIdx.x;
    if (cls_mode && cb >= 12) cb += 6;
    const int bn = cb * BN;
    const size_t bm = (cls_mode ? (size_t)NSLOT : 0) + (size_t)blockIdx.y * BM;
    const __half* __restrict__ A = g_Xh[layer & 1];

    float acc[4][4][4];
#pragma unroll
    for (int a = 0; a < 4; a++)
#pragma unroll
        for (int b = 0; b < 4; b++)
#pragma unroll
            for (int c = 0; c < 4; c++) acc[a][b][c] = 0.f;

    const int KT = 24;
    load_tile(sb + 0 * STAGE, tid, A, bm, HH, 0, g_Wth, bn, HH, 0);
    asm volatile("cp.async.commit_group;");
    load_tile(sb + 1 * STAGE, tid, A, bm, HH, BK, g_Wth, bn, HH, BK);
    asm volatile("cp.async.commit_group;");
    for (int kt = 0; kt < KT; kt++) {
        asm volatile("cp.async.wait_group 1;" ::: "memory");
        __syncthreads();
        if (kt + 2 < KT) {
            int nk = kt + 2;
            load_tile(sb + (nk % 3) * STAGE, tid, A, bm, HH, nk * BK,
                      g_Wth, bn, HH, nk * BK);
        }
        asm volatile("cp.async.commit_group;");
        compute_tile(sb + (kt % 3) * STAGE, wm, wn, lane, acc);
    }

    const int gid = lane >> 2, tig = lane & 3;
#pragma unroll
    for (int mt = 0; mt < 4; mt++) {
        size_t r0 = bm + wm * 64 + mt * 16 + gid;
#pragma unroll
        for (int nt = 0; nt < 4; nt++) {
            int col = bn + wn * 32 + nt * 8 + tig * 2;
            float2 bia = *(const float2*)(g_bcat + col);
            float2 v0 = make_float2(acc[mt][nt][0] + bia.x, acc[mt][nt][1] + bia.y);
            float2 v1 = make_float2(acc[mt][nt][2] + bia.x, acc[mt][nt][3] + bia.y);
            *(float2*)(g_Y + r0 * NW + col) = v0;
            *(float2*)(g_Y + (r0 + 8) * NW + col) = v1;
        }
    }
}

// ---------------- GEMM 2: gate = sigmoid([U|X] @ Wg + bg), fused residual ----------------
__global__ void __launch_bounds__(NTHREADS, 2) k_gemm_gate(int layer, const float* __restrict__ bg) {
    extern __shared__ __align__(128) char smem[];
    uint32_t sb = s2u(smem);
    const int tid = threadIdx.x, lane = tid & 31, wid = tid >> 5;
    const int wm = wid >> 2, wn = wid & 3;
    const int bn = blockIdx.x * BN;
    const size_t bm = (size_t)blockIdx.y * BM;
    const __half* __restrict__ Xh = g_Xh[layer & 1];
    const float* __restrict__ Xf = g_X[layer & 1];
    float* __restrict__ Nf = g_X[(layer + 1) & 1];
    __half* __restrict__ Nh = g_Xh[(layer + 1) & 1];

    float acc[4][4][4];
#pragma unroll
    for (int a = 0; a < 4; a++)
#pragma unroll
        for (int b = 0; b < 4; b++)
#pragma unroll
            for (int c = 0; c < 4; c++) acc[a][b][c] = 0.f;

    const int KT = 48;
    load_tile(sb + 0 * STAGE, tid, g_Uh, bm, HH, 0, g_Gth, bn, 2 * HH, 0);
    asm volatile("cp.async.commit_group;");
    load_tile(sb + 1 * STAGE, tid, g_Uh, bm, HH, BK, g_Gth, bn, 2 * HH, BK);
    asm volatile("cp.async.commit_group;");
    for (int kt = 0; kt < KT; kt++) {
        asm volatile("cp.async.wait_group 1;" ::: "memory");
        __syncthreads();
        if (kt + 2 < KT) {
            int nk = kt + 2;
            const __half* as = (nk < 24) ? g_Uh : Xh;
            int ak = (nk < 24) ? nk * BK : (nk - 24) * BK;
            load_tile(sb + (nk % 3) * STAGE, tid, as, bm, HH, ak,
                      g_Gth, bn, 2 * HH, nk * BK);
        }
        asm volatile("cp.async.commit_group;");
        compute_tile(sb + (kt % 3) * STAGE, wm, wn, lane, acc);
    }

    const int gid = lane >> 2, tig = lane & 3;
#pragma unroll
    for (int mt = 0; mt < 4; mt++) {
        size_t r0 = bm + wm * 64 + mt * 16 + gid;
#pragma unroll
        for (int nt = 0; nt < 4; nt++) {
            int col = bn + wn * 32 + nt * 8 + tig * 2;
            float2 bia = *(const float2*)(bg + col);
#pragma unroll
            for (int h = 0; h < 2; h++) {
                size_t row = r0 + h * 8;
                size_t base = row * HH + col;
                float rr0 = acc[mt][nt][h * 2 + 0] + bia.x;
                float rr1 = acc[mt][nt][h * 2 + 1] + bia.y;
                float g0 = 1.f / (1.f + __expf(-rr0));
                float g1 = 1.f / (1.f + __expf(-rr1));
                float2 uv = *(const float2*)(g_U + base);
                float2 xv = *(const float2*)(Xf + base);
                float n0 = fmaxf(uv.x, 0.f) * g0 + xv.x * (1.f - g0);
                float n1 = fmaxf(uv.y, 0.f) * g1 + xv.y * (1.f - g1);
                *(float2*)(Nf + base) = make_float2(n0, n1);
                *(__half2*)(Nh + base) = __floats2half2_rn(n0, n1);
            }
        }
    }
}

// ---------------- mixing v2: register-resident, sync-free phases ----------------
// grid (BB, HH/128), 128 threads; thread t owns column k0+t.
__global__ void __launch_bounds__(128) k_mix(const float* __restrict__ a_cur,
                                             const float* __restrict__ a_slot,
                                             const float* __restrict__ a_last,
                                             const float* __restrict__ a_dom) {
    const int b = blockIdx.x;
    const int k = blockIdx.y * 128 + threadIdx.x;
    const int t = threadIdx.x;

    __shared__ float sCur[SS*CC], sLast[SS*CC], sSlot[SS*SS], sDom[SS*SS];
    __shared__ float invColCur[CC], invColLast[CC];
    __shared__ float invRowCur[SS], invRowSlot[SS], invRowLast[SS], invRowDom[SS];

    for (int i = t; i < SS*CC; i += 128) {
        sCur[i]  = a_cur [(size_t)b*SS*CC + i];
        sLast[i] = a_last[(size_t)b*SS*CC + i];
    }
    for (int i = t; i < SS*SS; i += 128) {
        sSlot[i] = a_slot[(size_t)b*SS*SS + i];
        sDom[i]  = a_dom [(size_t)b*SS*SS + i];
    }
    __syncthreads();
    if (t < CC) {
        float s1 = 0.f, s2 = 0.f;
        for (int s = 0; s < SS; s++) { s1 += sCur[s*CC+t]; s2 += sLast[s*CC+t]; }
        invColCur[t]  = 1.f / (s1 + EPSV);
        invColLast[t] = 1.f / (s2 + EPSV);
    } else if (t >= 32 && t < 32 + SS) {
        int s = t - 32; float s1 = 0.f, s2 = 0.f;
        for (int c = 0; c < CC; c++) { s1 += sCur[s*CC+c]; s2 += sLast[s*CC+c]; }
        invRowCur[s]  = 1.f / (s1 + EPSV);
        invRowLast[s] = 1.f / (s2 + EPSV);
    } else if (t >= 64 && t < 64 + SS) {
        int s = t - 64; float s1 = 0.f, s2 = 0.f;
        for (int j = 0; j < SS; j++) { s1 += sSlot[s*SS+j]; s2 += sDom[s*SS+j]; }
        invRowSlot[s] = 1.f / (s1 + EPSV);
        invRowDom[s]  = 1.f / (s2 + EPSV);
    }
    __syncthreads();

    // ---- Phase A: cls rows. y1 = rel_slots blk1, y3 = rel_slots blk3 ----
    {
        float y1[SS], y3[SS];
#pragma unroll
        for (int s = 0; s < SS; s++) {
            size_t base = (size_t)(b*SS + s) * NW + k;
            y1[s] = g_Y[base + 1*HH];
            y3[s] = g_Y[base + 3*HH];
        }
#pragma unroll
        for (int c = 0; c < CC; c++) {
            float a1 = 0.f, a3 = 0.f;
#pragma unroll
            for (int s = 0; s < SS; s++) {
                a1 += sCur[s*CC+c]  * y1[s];
                a3 += sLast[s*CC+c] * y3[s];
            }
            size_t crow = (size_t)NSLOT + (size_t)b*CC + c;
            float v = g_Y[crow * NW + k] + invColCur[c]*a1 + invColLast[c]*a3;
            size_t idx = crow * HH + k;
            g_U[idx] = v;
            g_Uh[idx] = __float2half_rn(v);
        }
    }

    // ---- Phase B: slot rows ----
    {
        float rc1[CC], rc3[CC];
#pragma unroll
        for (int c = 0; c < CC; c++) {
            size_t base = ((size_t)NSLOT + (size_t)b*CC + c) * NW + k;
            rc1[c] = g_Y[base + 1*HH];
            rc3[c] = g_Y[base + 3*HH];
        }
        float rs2[SS], rs4[SS];
#pragma unroll
        for (int s = 0; s < SS; s++) {
            size_t base = (size_t)(b*SS + s) * NW + k;
            rs2[s] = g_Y[base + 2*HH];
            rs4[s] = g_Y[base + 4*HH];
        }
#pragma unroll
        for (int s = 0; s < SS; s++) {
            float ac = 0.f, al = 0.f;
#pragma unroll
            for (int c = 0; c < CC; c++) {
                ac += sCur[s*CC+c]  * rc1[c];
                al += sLast[s*CC+c] * rc3[c];
            }
            float a2 = 0.f, a4 = 0.f;
#pragma unroll
            for (int j = 0; j < SS; j++) {
                a2 += sSlot[s*SS+j] * rs2[j];
                a4 += sDom[s*SS+j]  * rs4[j];
            }
            size_t srow = (size_t)(b*SS + s);
            float v = g_Y[srow * NW + k]
                    + invRowCur[s]*ac + invRowSlot[s]*a2
                    + invRowLast[s]*al + invRowDom[s]*a4;
            size_t idx = srow * HH + k;
            g_U[idx] = v;
            g_Uh[idx] = __float2half_rn(v);
        }
    }
}

// ---------------- output ----------------
__global__ void k_out(float* __restrict__ out) {
    size_t i = (size_t)blockIdx.x * blockDim.x + threadIdx.x;
    const size_t total = (size_t)BB * 15 * HH;
    if (i >= total) return;
    int k = (int)(i % HH);
    size_t r = i / HH;
    int c = (int)(r % 15) + 1;
    int b = (int)(r / 15);
    out[i] = g_X[0][((size_t)NSLOT + (size_t)b*CC + c) * HH + k];
}

// ---------------- launch ----------------
extern "C" void kernel_launch(void* const* d_in, const int* in_sizes, int n_in,
                              void* d_out, int out_size) {
    const float* slots  = (const float*)d_in[0];
    const float* cls    = (const float*)d_in[1];
    const float* a_cur  = (const float*)d_in[2];
    const float* a_slot = (const float*)d_in[3];
    const float* a_last = (const float*)d_in[4];
    const float* a_dom  = (const float*)d_in[5];
    const float* W_r    = (const float*)d_in[6];
    const float* b_r    = (const float*)d_in[7];
    const float* W_s    = (const float*)d_in[8];
    const float* b_s    = (const float*)d_in[9];
    const float* W_g    = (const float*)d_in[10];
    const float* b_g    = (const float*)d_in[11];
    float* out = (float*)d_out;

    cudaFuncSetAttribute(k_gemm_proj, cudaFuncAttributeMaxDynamicSharedMemorySize, SMEM_TOTAL);
    cudaFuncSetAttribute(k_gemm_gate, cudaFuncAttributeMaxDynamicSharedMemorySize, SMEM_TOTAL);

    {
        size_t n = (size_t)NROW * HH;
        k_init<<<(unsigned)((n + 1023) / 1024), 1024>>>(slots, cls);
    }
    {
        size_t n = (size_t)NW * HH;
        k_packW<<<(unsigned)((n + 1023) / 1024), 1024>>>(W_s, b_s, W_r, b_r);
    }
    {
        size_t n = (size_t)HH * 2 * HH;
        k_packG<<<(unsigned)((n + 1023) / 1024), 1024>>>(W_g);
    }
    for (int layer = 0; layer < 2; layer++) {
        k_gemm_proj<<<dim3(NW/BN, NSLOT/BM), NTHREADS, SMEM_TOTAL>>>(layer, 0);
        k_gemm_proj<<<dim3(18, NCLS/BM), NTHREADS, SMEM_TOTAL>>>(layer, 1);
        k_mix<<<dim3(BB, HH/128), 128>>>(a_cur, a_slot, a_last, a_dom);
        k_gemm_gate<<<dim3(HH/BN, NROW/BM), NTHREADS, SMEM_TOTAL>>>(layer, b_g);
    }
    {
        size_t n = (size_t)BB * 15 * HH;
        k_out<<<(unsigned)((n + 255) / 256), 256>>>(out);
    }
}

// round 15
// speedup vs baseline: 2.1270x; 2.1270x over previous
#include <cuda_runtime.h>
#include <cuda_fp16.h>
#include <math.h>
#include <stdint.h>

#define BB 512
#define SS 30
#define CC 16
#define HH 768
#define NW 3840
#define NSLOT 15360
#define NCLS 8192
#define NROW 23552
#define EPSV 1e-5f

// GEMM tiling (fp16 single-term HMMA) — round-13 validated skeleton
#define BM 128
#define BN 128
#define BK 32
#define NTHREADS 256
#define TILE_BYTES (128*32*2)           // 8192 per matrix tile
#define OFF_A 0
#define OFF_B TILE_BYTES
#define STAGE  (2*TILE_BYTES)           // 16384
#define NSTAGE 3
#define SMEM_TOTAL (NSTAGE*STAGE)       // 49152 -> 2 CTAs/SM

// ---------------- scratch (__device__ globals; no allocations) ----------------
__device__ __align__(128) float  g_X[2][(size_t)NROW*HH];
__device__ __align__(128) __half g_Xh[2][(size_t)NROW*HH];
__device__ __align__(128) float  g_U[(size_t)NROW*HH];
__device__ __align__(128) __half g_Uh[(size_t)NROW*HH];
__device__ __align__(128) __half g_Y[(size_t)NROW*NW];      // fp16 Y (write-once, read-once)
__device__ __align__(128) __half g_Wth[(size_t)NW*HH];      // [NW][HH]  B^T proj
__device__ __align__(128) __half g_Gth[(size_t)HH*2*HH];    // [HH][2*HH] B^T gate
__device__ float g_bcat[NW];

// ---------------- PTX helpers ----------------
__device__ __forceinline__ uint32_t s2u(const void* p) {
    uint32_t a;
    asm("{ .reg .u64 t; cvta.to.shared.u64 t, %1; cvt.u32.u64 %0, t; }" : "=r"(a) : "l"(p));
    return a;
}
__device__ __forceinline__ void cpa16(uint32_t s, const void* g) {
    asm volatile("cp.async.cg.shared.global [%0], [%1], 16;" :: "r"(s), "l"(g));
}
__device__ __forceinline__ void ldsm_x4(uint32_t addr, uint32_t* r) {
    asm volatile("ldmatrix.sync.aligned.m8n8.x4.shared.b16 {%0,%1,%2,%3}, [%4];"
        : "=r"(r[0]), "=r"(r[1]), "=r"(r[2]), "=r"(r[3]) : "r"(addr));
}
__device__ __forceinline__ void mma_f16(float* d, const uint32_t* a, const uint32_t* b) {
    asm volatile("mma.sync.aligned.m16n8k16.row.col.f32.f16.f16.f32 "
        "{%0,%1,%2,%3}, {%4,%5,%6,%7}, {%8,%9}, {%0,%1,%2,%3};"
        : "+f"(d[0]), "+f"(d[1]), "+f"(d[2]), "+f"(d[3])
        : "r"(a[0]), "r"(a[1]), "r"(a[2]), "r"(a[3]), "r"(b[0]), "r"(b[1]));
}

// half-row swizzle for 64B rows packed 2-per-128B line (validated):
__device__ __forceinline__ uint32_t swz64(int row, int c) {
    return (uint32_t)(((row >> 1) << 7) + (((((row & 1) << 2) + c) ^ ((row >> 1) & 7)) << 4));
}

// ---------------- init / pack ----------------
__global__ void k_init(const float* __restrict__ slots, const float* __restrict__ cls) {
    size_t i = (size_t)blockIdx.x * blockDim.x + threadIdx.x;
    if (i >= (size_t)NROW * HH) return;
    const size_t n0 = (size_t)NSLOT * HH;
    float v = (i < n0) ? slots[i] : cls[i - n0];
    g_X[0][i] = v;
    g_Xh[0][i] = __float2half_rn(v);
}
__global__ void k_packW(const float* __restrict__ Ws, const float* __restrict__ bs,
                        const float* __restrict__ Wr, const float* __restrict__ br) {
    size_t i = (size_t)blockIdx.x * blockDim.x + threadIdx.x;
    if (i < (size_t)NW * HH) {
        int j = (int)(i / HH);
        int h = (int)(i % HH);
        int p = j / HH;
        int n = j % HH;
        float w = (p == 0) ? Ws[(size_t)h * HH + n]
                           : Wr[((size_t)(p - 1) * HH + h) * HH + n];
        g_Wth[i] = __float2half_rn(w);
    }
    if (i < NW) {
        int p = (int)(i / HH), n = (int)(i % HH);
        g_bcat[i] = (p == 0) ? bs[n] : br[(size_t)(p - 1) * HH + n];
    }
}
__global__ void k_packG(const float* __restrict__ Wg) {
    size_t i = (size_t)blockIdx.x * blockDim.x + threadIdx.x;
    if (i >= (size_t)HH * 2 * HH) return;
    int j = (int)(i / (2 * HH));
    int k = (int)(i % (2 * HH));
    g_Gth[i] = __float2half_rn(Wg[(size_t)k * HH + j]);
}

// ---------------- stage loader: 128x32 fp16 tiles, half-row swizzled ----------------
__device__ __forceinline__ void load_tile(
    uint32_t stg, int tid,
    const __half* __restrict__ A, size_t a_row0, int a_ld, int ak,
    const __half* __restrict__ B, size_t b_row0, int b_ld, int bk) {
#pragma unroll
    for (int t = 0; t < 2; t++) {
        int id = tid + t * NTHREADS;
        int row = id >> 2, c = id & 3;
        uint32_t so = swz64(row, c);
        cpa16(stg + OFF_A + so, A + (a_row0 + row) * (size_t)a_ld + ak + (c << 3));
        cpa16(stg + OFF_B + so, B + (b_row0 + row) * (size_t)b_ld + bk + (c << 3));
    }
}

// ---------------- per-BK-tile compute: single-term fp16 ----------------
__device__ __forceinline__ void compute_tile(uint32_t stg, int wm, int wn, int lane,
                                             float acc[4][4][4]) {
#pragma unroll
    for (int kk = 0; kk < 2; kk++) {
        uint32_t bh[4][2];
        {
            int brow = wn * 32 + (lane >> 4) * 8 + (lane & 7);
            int bc = kk * 2 + ((lane >> 3) & 1);
            uint32_t base = swz64(brow, bc);
#pragma unroll
            for (int p = 0; p < 2; p++) {
                uint32_t r[4];
                ldsm_x4(stg + OFF_B + base + p * 1024, r);
                bh[2*p][0] = r[0]; bh[2*p][1] = r[1];
                bh[2*p+1][0] = r[2]; bh[2*p+1][1] = r[3];
            }
        }
        const int arow = wm * 64 + (lane & 15);
        const int ac = kk * 2 + (lane >> 4);
        uint32_t abase = swz64(arow, ac);
        uint32_t ah[4][4];
#pragma unroll
        for (int mt = 0; mt < 4; mt++)
            ldsm_x4(stg + OFF_A + abase + mt * 1024, ah[mt]);
#pragma unroll
        for (int mt = 0; mt < 4; mt++)
#pragma unroll
            for (int nt = 0; nt < 4; nt++)
                mma_f16(acc[mt][nt], ah[mt], bh[nt]);
    }
}

// ---------------- GEMM 1: Y = X @ Wcat + bcat (fp16 output) ----------------
__global__ void __launch_bounds__(NTHREADS, 2) k_gemm_proj(int layer, int cls_mode) {
    extern __shared__ __align__(128) char smem[];
    uint32_t sb = s2u(smem);
    const int tid = threadIdx.x, lane = tid & 31, wid = tid >> 5;
    const int wm = wid >> 2, wn = wid & 3;
    int cb = blockIdx.x;
    if (cls_mode && cb >= 12) cb += 6;
    const int bn = cb * BN;
    const size_t bm = (cls_mode ? (size_t)NSLOT : 0) + (size_t)blockIdx.y * BM;
    const __half* __restrict__ A = g_Xh[layer & 1];

    float acc[4][4][4];
#pragma unroll
    for (int a = 0; a < 4; a++)
#pragma unroll
        for (int b = 0; b < 4; b++)
#pragma unroll
            for (int c = 0; c < 4; c++) acc[a][b][c] = 0.f;

    const int KT = 24;
    load_tile(sb + 0 * STAGE, tid, A, bm, HH, 0, g_Wth, bn, HH, 0);
    asm volatile("cp.async.commit_group;");
    load_tile(sb + 1 * STAGE, tid, A, bm, HH, BK, g_Wth, bn, HH, BK);
    asm volatile("cp.async.commit_group;");
    for (int kt = 0; kt < KT; kt++) {
        asm volatile("cp.async.wait_group 1;" ::: "memory");
        __syncthreads();
        if (kt + 2 < KT) {
            int nk = kt + 2;
            load_tile(sb + (nk % 3) * STAGE, tid, A, bm, HH, nk * BK,
                      g_Wth, bn, HH, nk * BK);
        }
        asm volatile("cp.async.commit_group;");
        compute_tile(sb + (kt % 3) * STAGE, wm, wn, lane, acc);
    }

    const int gid = lane >> 2, tig = lane & 3;
#pragma unroll
    for (int mt = 0; mt < 4; mt++) {
        size_t r0 = bm + wm * 64 + mt * 16 + gid;
#pragma unroll
        for (int nt = 0; nt < 4; nt++) {
            int col = bn + wn * 32 + nt * 8 + tig * 2;
            float2 bia = *(const float2*)(g_bcat + col);
            *(__half2*)(g_Y + r0 * NW + col) =
                __floats2half2_rn(acc[mt][nt][0] + bia.x, acc[mt][nt][1] + bia.y);
            *(__half2*)(g_Y + (r0 + 8) * NW + col) =
                __floats2half2_rn(acc[mt][nt][2] + bia.x, acc[mt][nt][3] + bia.y);
        }
    }
}

// ---------------- GEMM 2: gate = sigmoid([U|X] @ Wg + bg), fused residual ----------------
__global__ void __launch_bounds__(NTHREADS, 2) k_gemm_gate(int layer, const float* __restrict__ bg) {
    extern __shared__ __align__(128) char smem[];
    uint32_t sb = s2u(smem);
    const int tid = threadIdx.x, lane = tid & 31, wid = tid >> 5;
    const int wm = wid >> 2, wn = wid & 3;
    const int bn = blockIdx.x * BN;
    const size_t bm = (size_t)blockIdx.y * BM;
    const __half* __restrict__ Xh = g_Xh[layer & 1];
    const float* __restrict__ Xf = g_X[layer & 1];
    float* __restrict__ Nf = g_X[(layer + 1) & 1];
    __half* __restrict__ Nh = g_Xh[(layer + 1) & 1];

    float acc[4][4][4];
#pragma unroll
    for (int a = 0; a < 4; a++)
#pragma unroll
        for (int b = 0; b < 4; b++)
#pragma unroll
            for (int c = 0; c < 4; c++) acc[a][b][c] = 0.f;

    const int KT = 48;
    load_tile(sb + 0 * STAGE, tid, g_Uh, bm, HH, 0, g_Gth, bn, 2 * HH, 0);
    asm volatile("cp.async.commit_group;");
    load_tile(sb + 1 * STAGE, tid, g_Uh, bm, HH, BK, g_Gth, bn, 2 * HH, BK);
    asm volatile("cp.async.commit_group;");
    for (int kt = 0; kt < KT; kt++) {
        asm volatile("cp.async.wait_group 1;" ::: "memory");
        __syncthreads();
        if (kt + 2 < KT) {
            int nk = kt + 2;
            const __half* as = (nk < 24) ? g_Uh : Xh;
            int ak = (nk < 24) ? nk * BK : (nk - 24) * BK;
            load_tile(sb + (nk % 3) * STAGE, tid, as, bm, HH, ak,
                      g_Gth, bn, 2 * HH, nk * BK);
        }
        asm volatile("cp.async.commit_group;");
        compute_tile(sb + (kt % 3) * STAGE, wm, wn, lane, acc);
    }

    const int gid = lane >> 2, tig = lane & 3;
#pragma unroll
    for (int mt = 0; mt < 4; mt++) {
        size_t r0 = bm + wm * 64 + mt * 16 + gid;
#pragma unroll
        for (int nt = 0; nt < 4; nt++) {
            int col = bn + wn * 32 + nt * 8 + tig * 2;
            float2 bia = *(const float2*)(bg + col);
#pragma unroll
            for (int h = 0; h < 2; h++) {
                size_t row = r0 + h * 8;
                size_t base = row * HH + col;
                float rr0 = acc[mt][nt][h * 2 + 0] + bia.x;
                float rr1 = acc[mt][nt][h * 2 + 1] + bia.y;
                float g0 = 1.f / (1.f + __expf(-rr0));
                float g1 = 1.f / (1.f + __expf(-rr1));
                float2 uv = *(const float2*)(g_U + base);
                float2 xv = *(const float2*)(Xf + base);
                float n0 = fmaxf(uv.x, 0.f) * g0 + xv.x * (1.f - g0);
                float n1 = fmaxf(uv.y, 0.f) * g1 + xv.y * (1.f - g1);
                *(float2*)(Nf + base) = make_float2(n0, n1);
                *(__half2*)(Nh + base) = __floats2half2_rn(n0, n1);
            }
        }
    }
}

// ---------------- mixing (round-13 v1 structure; fp16 Y reads) ----------------
__global__ void __launch_bounds__(128) k_mix(const float* __restrict__ a_cur,
                                             const float* __restrict__ a_slot,
                                             const float* __restrict__ a_last,
                                             const float* __restrict__ a_dom) {
    const int b = blockIdx.x;
    const int k0 = blockIdx.y * 128;
    const int t = threadIdx.x;

    __shared__ float sCur[SS*CC], sLast[SS*CC], sSlot[SS*SS], sDom[SS*SS];
    __shared__ float invColCur[CC], invColLast[CC];
    __shared__ float invRowCur[SS], invRowSlot[SS], invRowLast[SS], invRowDom[SS];
    __shared__ float T0[SS*128];
    __shared__ float T1[SS*128];

    for (int i = t; i < SS*CC; i += 128) {
        sCur[i]  = a_cur [(size_t)b*SS*CC + i];
        sLast[i] = a_last[(size_t)b*SS*CC + i];
    }
    for (int i = t; i < SS*SS; i += 128) {
        sSlot[i] = a_slot[(size_t)b*SS*SS + i];
        sDom[i]  = a_dom [(size_t)b*SS*SS + i];
    }
    __syncthreads();
    if (t < CC) {
        float s1 = 0.f, s2 = 0.f;
        for (int s = 0; s < SS; s++) { s1 += sCur[s*CC+t]; s2 += sLast[s*CC+t]; }
        invColCur[t]  = 1.f / (s1 + EPSV);
        invColLast[t] = 1.f / (s2 + EPSV);
    } else if (t >= 32 && t < 32 + SS) {
        int s = t - 32; float s1 = 0.f, s2 = 0.f;
        for (int c = 0; c < CC; c++) { s1 += sCur[s*CC+c]; s2 += sLast[s*CC+c]; }
        invRowCur[s]  = 1.f / (s1 + EPSV);
        invRowLast[s] = 1.f / (s2 + EPSV);
    } else if (t >= 64 && t < 64 + SS) {
        int s = t - 64; float s1 = 0.f, s2 = 0.f;
        for (int j = 0; j < SS; j++) { s1 += sSlot[s*SS+j]; s2 += sDom[s*SS+j]; }
        invRowSlot[s] = 1.f / (s1 + EPSV);
        invRowDom[s]  = 1.f / (s2 + EPSV);
    }
    __syncthreads();

    // Phase A: cls rows
    for (int s = 0; s < SS; s++) {
        size_t base = (size_t)(b*SS + s) * NW + k0 + t;
        T0[s*128 + t] = __half2float(g_Y[base + 1*HH]);
        T1[s*128 + t] = __half2float(g_Y[base + 3*HH]);
    }
    __syncthreads();
    for (int c = 0; c < CC; c++) {
        float a1 = 0.f, a3 = 0.f;
#pragma unroll
        for (int s = 0; s < SS; s++) {
            a1 += sCur[s*CC+c]  * T0[s*128+t];
            a3 += sLast[s*CC+c] * T1[s*128+t];
        }
        size_t crow = (size_t)NSLOT + (size_t)b*CC + c;
        float v = __half2float(g_Y[crow * NW + k0 + t]) + invColCur[c]*a1 + invColLast[c]*a3;
        size_t idx = crow * HH + k0 + t;
        g_U[idx] = v;
        g_Uh[idx] = __float2half_rn(v);
    }
    __syncthreads();

    // Phase B1
    for (int c = 0; c < CC; c++)
        T0[c*128 + t] = __half2float(g_Y[((size_t)NSLOT + (size_t)b*CC + c) * NW + 1*HH + k0 + t]);
    for (int s = 0; s < SS; s++)
        T1[s*128 + t] = __half2float(g_Y[(size_t)(b*SS + s) * NW + 2*HH + k0 + t]);
    __syncthreads();
    float acc[SS];
#pragma unroll
    for (int s = 0; s < SS; s++) {
        float ac = 0.f, as_ = 0.f;
#pragma unroll
        for (int c = 0; c < CC; c++) ac  += sCur[s*CC+c]  * T0[c*128+t];
#pragma unroll
        for (int j = 0; j < SS; j++) as_ += sSlot[s*SS+j] * T1[j*128+t];
        acc[s] = invRowCur[s]*ac + invRowSlot[s]*as_;
    }
    __syncthreads();

    // Phase B2
    for (int c = 0; c < CC; c++)
        T0[c*128 + t] = __half2float(g_Y[((size_t)NSLOT + (size_t)b*CC + c) * NW + 3*HH + k0 + t]);
    for (int s = 0; s < SS; s++)
        T1[s*128 + t] = __half2float(g_Y[(size_t)(b*SS + s) * NW + 4*HH + k0 + t]);
    __syncthreads();
#pragma unroll
    for (int s = 0; s < SS; s++) {
        float ac = 0.f, as_ = 0.f;
#pragma unroll
        for (int c = 0; c < CC; c++) ac  += sLast[s*CC+c] * T0[c*128+t];
#pragma unroll
        for (int j = 0; j < SS; j++) as_ += sDom[s*SS+j]  * T1[j*128+t];
        acc[s] += invRowLast[s]*ac + invRowDom[s]*as_;
        size_t srow = (size_t)(b*SS + s);
        float v = __half2float(g_Y[srow * NW + k0 + t]) + acc[s];
        size_t idx = srow * HH + k0 + t;
        g_U[idx] = v;
        g_Uh[idx] = __float2half_rn(v);
    }
}

// ---------------- output ----------------
__global__ void k_out(float* __restrict__ out) {
    size_t i = (size_t)blockIdx.x * blockDim.x + threadIdx.x;
    const size_t total = (size_t)BB * 15 * HH;
    if (i >= total) return;
    int k = (int)(i % HH);
    size_t r = i / HH;
    int c = (int)(r % 15) + 1;
    int b = (int)(r / 15);
    out[i] = g_X[0][((size_t)NSLOT + (size_t)b*CC + c) * HH + k];
}

// ---------------- launch ----------------
extern "C" void kernel_launch(void* const* d_in, const int* in_sizes, int n_in,
                              void* d_out, int out_size) {
    const float* slots  = (const float*)d_in[0];
    const float* cls    = (const float*)d_in[1];
    const float* a_cur  = (const float*)d_in[2];
    const float* a_slot = (const float*)d_in[3];
    const float* a_last = (const float*)d_in[4];
    const float* a_dom  = (const float*)d_in[5];
    const float* W_r    = (const float*)d_in[6];
    const float* b_r    = (const float*)d_in[7];
    const float* W_s    = (const float*)d_in[8];
    const float* b_s    = (const float*)d_in[9];
    const float* W_g    = (const float*)d_in[10];
    const float* b_g    = (const float*)d_in[11];
    float* out = (float*)d_out;

    cudaFuncSetAttribute(k_gemm_proj, cudaFuncAttributeMaxDynamicSharedMemorySize, SMEM_TOTAL);
    cudaFuncSetAttribute(k_gemm_gate, cudaFuncAttributeMaxDynamicSharedMemorySize, SMEM_TOTAL);

    {
        size_t n = (size_t)NROW * HH;
        k_init<<<(unsigned)((n + 1023) / 1024), 1024>>>(slots, cls);
    }
    {
        size_t n = (size_t)NW * HH;
        k_packW<<<(unsigned)((n + 1023) / 1024), 1024>>>(W_s, b_s, W_r, b_r);
    }
    {
        size_t n = (size_t)HH * 2 * HH;
        k_packG<<<(unsigned)((n + 1023) / 1024), 1024>>>(W_g);
    }
    for (int layer = 0; layer < 2; layer++) {
        k_gemm_proj<<<dim3(NW/BN, NSLOT/BM), NTHREADS, SMEM_TOTAL>>>(layer, 0);
        k_gemm_proj<<<dim3(18, NCLS/BM), NTHREADS, SMEM_TOTAL>>>(layer, 1);
        k_mix<<<dim3(BB, HH/128), 128>>>(a_cur, a_slot, a_last, a_dom);
        k_gemm_gate<<<dim3(HH/BN, NROW/BM), NTHREADS, SMEM_TOTAL>>>(layer, b_g);
    }
    {
        size_t n = (size_t)BB * 15 * HH;
        k_out<<<(unsigned)((n + 255) / 256), 256>>>(out);
    }
}